// round 2
// baseline (speedup 1.0000x reference)
#include <cuda_runtime.h>
#include <math.h>

// ---------------------------------------------------------------------------
// DivFreeNetwork: u_i(z) = sum_j dA_ij/dz_j, A antisymmetric built from an MLP.
// Forward-mode: 5 rows per point (primal + 4 tangents) through shared weights.
//   layer0: primal preact = x@W0+b0 ; tangent_j preact = W0[j,:]
//   hidden: PRE = ACT @ Wh[l]  (+bh[l] on primal rows only)
//           ACT_primal = silu(p); ACT_tan_j = silu'(p) * PRE_tan_j
//   out:    OUT = ACT @ Wout (+bout on primal rows)
//   head:   softmax-mixture derivative + antisymmetric trace assembly
// ---------------------------------------------------------------------------

#define DM 1024
#define ODIM 448
#define NLAY 4
#define MAXB 65536
#define MROWS (MAXB * 5)

__device__ float g_ACT[(size_t)MROWS * DM];
__device__ float g_PRE[(size_t)MROWS * DM];
__device__ float g_OUT[(size_t)MROWS * ODIM];

__device__ __forceinline__ float sigf(float p) { return 1.0f / (1.0f + expf(-p)); }

// ---------------- layer 0: fused input GEMV + activation -------------------
__global__ void layer0_kernel(const float* __restrict__ x,
                              const float* __restrict__ W0,
                              const float* __restrict__ b0,
                              float* __restrict__ ACT, int B)
{
    int idx = blockIdx.x * blockDim.x + threadIdx.x;
    if (idx >= B * DM) return;
    int b = idx >> 10;
    int c = idx & 1023;
    float x0 = __ldg(x + b * 4 + 0);
    float x1 = __ldg(x + b * 4 + 1);
    float x2 = __ldg(x + b * 4 + 2);
    float x3 = __ldg(x + b * 4 + 3);
    float w0 = W0[c], w1 = W0[1024 + c], w2 = W0[2048 + c], w3 = W0[3072 + c];
    float p = fmaf(x0, w0, fmaf(x1, w1, fmaf(x2, w2, fmaf(x3, w3, b0[c]))));
    float sg = sigf(p);
    float act = p * sg;
    float d = sg * fmaf(p, 1.0f - sg, 1.0f);   // silu'(p)
    size_t base = (size_t)b * (5 * DM) + c;
    ACT[base]            = act;
    ACT[base + 1 * DM]   = d * w0;
    ACT[base + 2 * DM]   = d * w1;
    ACT[base + 3 * DM]   = d * w2;
    ACT[base + 4 * DM]   = d * w3;
}

// ---------------- activation kernel (hidden layers) ------------------------
__global__ void act_kernel(const float* __restrict__ PRE,
                           float* __restrict__ ACT, int B)
{
    int idx = blockIdx.x * blockDim.x + threadIdx.x;
    if (idx >= B * DM) return;
    int b = idx >> 10;
    int c = idx & 1023;
    size_t base = (size_t)b * (5 * DM) + c;
    float p = PRE[base];
    float sg = sigf(p);
    ACT[base] = p * sg;
    float d = sg * fmaf(p, 1.0f - sg, 1.0f);
    ACT[base + 1 * DM] = d * PRE[base + 1 * DM];
    ACT[base + 2 * DM] = d * PRE[base + 2 * DM];
    ACT[base + 3 * DM] = d * PRE[base + 3 * DM];
    ACT[base + 4 * DM] = d * PRE[base + 4 * DM];
}

// ---------------- fp32 SGEMM: C[M,N] = A[M,K] @ B[K,N] (+bias on rows%5==0) -
#define BM 128
#define BN 128
#define BK 16
__global__ __launch_bounds__(256)
void sgemm_bias(const float* __restrict__ A, const float* __restrict__ Bw,
                const float* __restrict__ bias, float* __restrict__ C,
                int M, int N, int K)
{
    __shared__ float As[BK][BM];
    __shared__ float Bs[BK][BN];
    int tid = threadIdx.x;
    int row0 = blockIdx.y * BM;
    int col0 = blockIdx.x * BN;
    int tr = tid >> 4;        // 0..15
    int tc = tid & 15;        // 0..15

    float acc[8][8];
#pragma unroll
    for (int i = 0; i < 8; i++)
#pragma unroll
        for (int j = 0; j < 8; j++) acc[i][j] = 0.0f;

    for (int k0 = 0; k0 < K; k0 += BK) {
        // load A tile (128x16), transpose into As[k][m]
#pragma unroll
        for (int it = 0; it < 2; it++) {
            int s = tid + it * 256;          // 0..511 float4 slots
            int r = s >> 2;
            int kq = (s & 3) * 4;
            float4 v = *(const float4*)(A + (size_t)(row0 + r) * K + k0 + kq);
            As[kq + 0][r] = v.x;
            As[kq + 1][r] = v.y;
            As[kq + 2][r] = v.z;
            As[kq + 3][r] = v.w;
        }
        // load B tile (16x128)
#pragma unroll
        for (int it = 0; it < 2; it++) {
            int s = tid + it * 256;
            int r = s >> 5;
            int c = (s & 31) * 4;
            int gc = col0 + c;
            float4 v = make_float4(0.f, 0.f, 0.f, 0.f);
            if (gc < N)
                v = *(const float4*)(Bw + (size_t)(k0 + r) * N + gc);
            *(float4*)&Bs[r][c] = v;
        }
        __syncthreads();
#pragma unroll
        for (int kk = 0; kk < BK; kk++) {
            float4 a0 = *(float4*)&As[kk][tr * 8];
            float4 a1 = *(float4*)&As[kk][tr * 8 + 4];
            float4 b0 = *(float4*)&Bs[kk][tc * 8];
            float4 b1 = *(float4*)&Bs[kk][tc * 8 + 4];
            float a[8] = {a0.x, a0.y, a0.z, a0.w, a1.x, a1.y, a1.z, a1.w};
            float b[8] = {b0.x, b0.y, b0.z, b0.w, b1.x, b1.y, b1.z, b1.w};
#pragma unroll
            for (int i = 0; i < 8; i++)
#pragma unroll
                for (int j = 0; j < 8; j++)
                    acc[i][j] = fmaf(a[i], b[j], acc[i][j]);
        }
        __syncthreads();
    }

#pragma unroll
    for (int i = 0; i < 8; i++) {
        int gr = row0 + tr * 8 + i;
        bool primal = (gr % 5) == 0;
#pragma unroll
        for (int j = 0; j < 8; j += 4) {
            int gc = col0 + tc * 8 + j;
            if (gc < N) {
                float4 v = make_float4(acc[i][j], acc[i][j + 1], acc[i][j + 2], acc[i][j + 3]);
                if (primal) {
                    v.x += bias[gc + 0];
                    v.y += bias[gc + 1];
                    v.z += bias[gc + 2];
                    v.w += bias[gc + 3];
                }
                *(float4*)(C + (size_t)gr * N + gc) = v;
            }
        }
    }
}

// ---------------- head: softmax-mixture derivative, warp per point ---------
__global__ void finalize_kernel(const float* __restrict__ OUT,
                                float* __restrict__ y, int B)
{
    int warp = (blockIdx.x * blockDim.x + threadIdx.x) >> 5;
    int lane = threadIdx.x & 31;
    if (warp >= B) return;
    const float* o = OUT + (size_t)warp * 5 * ODIM;

    // softmax over 64 logits (2 per lane)
    float l0 = o[lane], l1 = o[lane + 32];
    float m = fmaxf(l0, l1);
#pragma unroll
    for (int s = 16; s; s >>= 1) m = fmaxf(m, __shfl_xor_sync(0xFFFFFFFFu, m, s));
    float e0 = expf(l0 - m), e1 = expf(l1 - m);
    float S = e0 + e1;
#pragma unroll
    for (int s = 16; s; s >>= 1) S += __shfl_xor_sync(0xFFFFFFFFu, S, s);
    float s0 = e0 / S, s1 = e1 / S;

    float v0[6], v1[6];
#pragma unroll
    for (int t = 0; t < 6; t++) {
        v0[t] = o[64 + 6 * lane + t];
        v1[t] = o[64 + 6 * (lane + 32) + t];
    }

    float Dm[4][6];
#pragma unroll
    for (int j = 0; j < 4; j++) {
        const float* tj = o + (size_t)(j + 1) * ODIM;
        float g0 = tj[lane], g1 = tj[lane + 32];
        float dot = s0 * g0 + s1 * g1;
#pragma unroll
        for (int s = 16; s; s >>= 1) dot += __shfl_xor_sync(0xFFFFFFFFu, dot, s);
#pragma unroll
        for (int t = 0; t < 6; t++) {
            float dv0 = tj[64 + 6 * lane + t];
            float dv1 = tj[64 + 6 * (lane + 32) + t];
            float val = s0 * fmaf(g0 - dot, v0[t], dv0) + s1 * fmaf(g1 - dot, v1[t], dv1);
#pragma unroll
            for (int s = 16; s; s >>= 1) val += __shfl_xor_sync(0xFFFFFFFFu, val, s);
            Dm[j][t] = val;
        }
    }
    if (lane == 0) {
        // triu order: (0,1)(0,2)(0,3)(1,2)(1,3)(2,3); Dm[j][t] = da_t/dz_j
        float u0 =  Dm[1][0] + Dm[2][1] + Dm[3][2];
        float u1 = -Dm[0][0] + Dm[2][3] + Dm[3][4];
        float u2 = -Dm[0][1] - Dm[1][3] + Dm[3][5];
        float u3 = -Dm[0][2] - Dm[1][4] - Dm[2][5];
        float4 r = make_float4(u0 * 10.0f, u1, u2, u3);
        *(float4*)(y + (size_t)warp * 4) = r;
    }
}

// ---------------------------------------------------------------------------
extern "C" void kernel_launch(void* const* d_in, const int* in_sizes, int n_in,
                              void* d_out, int out_size)
{
    const float* x    = (const float*)d_in[0];
    const float* W0   = (const float*)d_in[1];
    const float* b0   = (const float*)d_in[2];
    const float* Wh   = (const float*)d_in[3];
    const float* bh   = (const float*)d_in[4];
    const float* Wout = (const float*)d_in[5];
    const float* bout = (const float*)d_in[6];
    float* y = (float*)d_out;

    int B = in_sizes[0] / 4;
    int M = B * 5;

    float *ACT, *PRE, *OUTB;
    cudaGetSymbolAddress((void**)&ACT, g_ACT);
    cudaGetSymbolAddress((void**)&PRE, g_PRE);
    cudaGetSymbolAddress((void**)&OUTB, g_OUT);

    // layer 0
    {
        int n = B * DM;
        layer0_kernel<<<(n + 255) / 256, 256>>>(x, W0, b0, ACT, B);
    }

    // hidden layers
    dim3 gH(DM / BN, M / BM);
    for (int l = 0; l < NLAY; l++) {
        sgemm_bias<<<gH, 256>>>(ACT, Wh + (size_t)l * DM * DM, bh + (size_t)l * DM,
                                PRE, M, DM, DM);
        int n = B * DM;
        act_kernel<<<(n + 255) / 256, 256>>>(PRE, ACT, B);
    }

    // output layer (N=448, grid.x covers with guards)
    dim3 gO((ODIM + BN - 1) / BN, M / BM);
    sgemm_bias<<<gO, 256>>>(ACT, Wout, bout, OUTB, M, ODIM, DM);

    // head
    finalize_kernel<<<(B * 32 + 255) / 256, 256>>>(OUTB, y, B);
}

// round 4
// speedup vs baseline: 2.6665x; 2.6665x over previous
#include <cuda_runtime.h>
#include <cuda_fp16.h>
#include <math.h>
#include <stdint.h>

// ===========================================================================
// DivFreeNetwork, forward-mode (primal + 4 tangents = 5 rows/point).
// GEMMs via mma.sync (HMMA) fp16 hi/lo split, 3 products, fp32 accumulate.
// (tcgen05 is unavailable: harness compiles via virtual arch compute_103.)
// ===========================================================================

#define DM 1024
#define ODIM 448
#define NLAY 4
#define MAXB 65536
#define MROWS (MAXB * 5)

__device__ __half g_Ah[(size_t)MROWS * DM];
__device__ __half g_Al[(size_t)MROWS * DM];
__device__ float  g_PRE[(size_t)MROWS * DM];
__device__ float  g_OUT[(size_t)MROWS * ODIM];
// transposed weights: Wh (4 x 1024 x 1024) then WoutT padded to 512 rows
__device__ __half g_WThi[(size_t)NLAY * DM * DM + 512 * DM];
__device__ __half g_WTlo[(size_t)NLAY * DM * DM + 512 * DM];

// ------------------------------- helpers -----------------------------------
__device__ __forceinline__ uint32_t smem_u32(const void* p) {
    uint32_t a;
    asm("{ .reg .u64 t; cvta.to.shared.u64 t, %1; cvt.u32.u64 %0, t; }" : "=r"(a) : "l"(p));
    return a;
}
#define SWZ(o) ((o) ^ (((o) >> 3) & 0x70))

__device__ __forceinline__ void cp16(uint32_t so, const void* g) {
    asm volatile("cp.async.cg.shared.global [%0], [%1], 16;" :: "r"(so), "l"(g));
}
__device__ __forceinline__ void ldsm4(uint32_t* r, uint32_t addr) {
    asm volatile("ldmatrix.sync.aligned.m8n8.x4.shared.b16 {%0,%1,%2,%3}, [%4];"
                 : "=r"(r[0]), "=r"(r[1]), "=r"(r[2]), "=r"(r[3]) : "r"(addr));
}
__device__ __forceinline__ void mma16816(float* c, const uint32_t* a, uint32_t b0, uint32_t b1) {
    asm volatile("mma.sync.aligned.m16n8k16.row.col.f32.f16.f16.f32 "
                 "{%0,%1,%2,%3}, {%4,%5,%6,%7}, {%8,%9}, {%0,%1,%2,%3};"
                 : "+f"(c[0]), "+f"(c[1]), "+f"(c[2]), "+f"(c[3])
                 : "r"(a[0]), "r"(a[1]), "r"(a[2]), "r"(a[3]), "r"(b0), "r"(b1));
}

__device__ __forceinline__ float sigf(float p) { return 1.0f / (1.0f + expf(-p)); }

__device__ __forceinline__ void store4split(__half* ph, __half* pl, float4 v) {
    __align__(8) __half h[4], l[4];
    float vv[4] = {v.x, v.y, v.z, v.w};
#pragma unroll
    for (int i = 0; i < 4; i++) {
        h[i] = __float2half(vv[i]);
        l[i] = __float2half(vv[i] - __half2float(h[i]));
    }
    *(uint2*)ph = *(uint2*)h;
    *(uint2*)pl = *(uint2*)l;
}

// ------------------ prep: transpose + hi/lo split of weights ----------------
__global__ void prep_transpose(const float* __restrict__ W,
                               __half* __restrict__ Thi,
                               __half* __restrict__ Tlo,
                               int Krows, int Ncols)
{
    __shared__ float t[32][33];
    const float* Wz = W + (size_t)blockIdx.z * Krows * Ncols;
    __half* Hz = Thi + (size_t)blockIdx.z * Ncols * Krows;
    __half* Lz = Tlo + (size_t)blockIdx.z * Ncols * Krows;
    int n0 = blockIdx.x * 32, k0 = blockIdx.y * 32;
    int tx = threadIdx.x, ty = threadIdx.y;
#pragma unroll
    for (int i = 0; i < 4; i++)
        t[ty + 8 * i][tx] = Wz[(size_t)(k0 + ty + 8 * i) * Ncols + n0 + tx];
    __syncthreads();
#pragma unroll
    for (int i = 0; i < 4; i++) {
        int n = n0 + ty + 8 * i;
        float v = t[tx][ty + 8 * i];
        __half h = __float2half(v);
        Hz[(size_t)n * Krows + k0 + tx] = h;
        Lz[(size_t)n * Krows + k0 + tx] = __float2half(v - __half2float(h));
    }
}

// ---------------- layer 0: fused input GEMV + activation -------------------
__global__ void layer0_kernel(const float* __restrict__ x,
                              const float* __restrict__ W0,
                              const float* __restrict__ b0,
                              __half* __restrict__ Ah,
                              __half* __restrict__ Al, int B)
{
    int idx = blockIdx.x * blockDim.x + threadIdx.x;
    if (idx >= B * 256) return;
    int b = idx >> 8;
    int c = (idx & 255) * 4;
    float x0 = __ldg(x + b * 4 + 0), x1 = __ldg(x + b * 4 + 1);
    float x2 = __ldg(x + b * 4 + 2), x3 = __ldg(x + b * 4 + 3);
    float4 w0 = *(const float4*)(W0 + c);
    float4 w1 = *(const float4*)(W0 + 1024 + c);
    float4 w2 = *(const float4*)(W0 + 2048 + c);
    float4 w3 = *(const float4*)(W0 + 3072 + c);
    float4 bb = *(const float4*)(b0 + c);
    float p[4], act[4], d[4];
    float wv[4][4] = {{w0.x, w1.x, w2.x, w3.x}, {w0.y, w1.y, w2.y, w3.y},
                      {w0.z, w1.z, w2.z, w3.z}, {w0.w, w1.w, w2.w, w3.w}};
    float bv[4] = {bb.x, bb.y, bb.z, bb.w};
#pragma unroll
    for (int i = 0; i < 4; i++) {
        p[i] = fmaf(x0, wv[i][0], fmaf(x1, wv[i][1], fmaf(x2, wv[i][2], fmaf(x3, wv[i][3], bv[i]))));
        float sg = sigf(p[i]);
        act[i] = p[i] * sg;
        d[i] = sg * fmaf(p[i], 1.0f - sg, 1.0f);
    }
    size_t base = (size_t)b * (5 * DM) + c;
    store4split(Ah + base, Al + base, make_float4(act[0], act[1], act[2], act[3]));
#pragma unroll
    for (int j = 0; j < 4; j++) {
        float4 t = make_float4(d[0] * wv[0][j], d[1] * wv[1][j], d[2] * wv[2][j], d[3] * wv[3][j]);
        store4split(Ah + base + (j + 1) * DM, Al + base + (j + 1) * DM, t);
    }
}

// ---------------- activation: PRE fp32 -> ACT half hi/lo -------------------
__global__ void act_kernel(const float* __restrict__ PRE,
                           __half* __restrict__ Ah,
                           __half* __restrict__ Al, int B)
{
    int idx = blockIdx.x * blockDim.x + threadIdx.x;
    if (idx >= B * 256) return;
    int b = idx >> 8;
    int c = (idx & 255) * 4;
    size_t base = (size_t)b * (5 * DM) + c;
    float4 p = *(const float4*)(PRE + base);
    float pv[4] = {p.x, p.y, p.z, p.w}, av[4], dv[4];
#pragma unroll
    for (int i = 0; i < 4; i++) {
        float sg = sigf(pv[i]);
        av[i] = pv[i] * sg;
        dv[i] = sg * fmaf(pv[i], 1.0f - sg, 1.0f);
    }
    store4split(Ah + base, Al + base, make_float4(av[0], av[1], av[2], av[3]));
#pragma unroll
    for (int j = 1; j < 5; j++) {
        float4 t = *(const float4*)(PRE + base + j * DM);
        t.x *= dv[0]; t.y *= dv[1]; t.z *= dv[2]; t.w *= dv[3];
        store4split(Ah + base + j * DM, Al + base + j * DM, t);
    }
}

// ---------------- HMMA GEMM: C[M,N] = (Ahi+Alo) @ (Bhi+Blo)^T --------------
// A: [M][K] half pairs (row-major); B: WT [N][K] half pairs (row-major = B col-major)
// bias added on global rows with gr%5==0.
// Block 128x128, BK=64 halves (128B rows, SW128 swizzle), 2-stage cp.async.
#define STG 65536               // 4 planes x 16KB per stage

__device__ __forceinline__ void load_stage(uint32_t sb,
    const __half* Ah, const __half* Al, const __half* Bh, const __half* Bl,
    int row0, int col0, int k0, int K, int tid)
{
    const __half* gs[4] = {Ah, Al, Bh, Bl};
#pragma unroll
    for (int pl = 0; pl < 4; pl++) {
        const __half* g = gs[pl];
        int r0 = (pl < 2) ? row0 : col0;
        uint32_t pb = sb + pl * 16384;
#pragma unroll
        for (int it = 0; it < 4; it++) {
            int t = tid + it * 256;
            int r = t >> 3, cc = t & 7;
            cp16(pb + SWZ(r * 128 + cc * 16), g + (size_t)(r0 + r) * K + k0 + cc * 8);
        }
    }
    asm volatile("cp.async.commit_group;" ::: "memory");
}

__global__ void __launch_bounds__(256, 1)
gemm_mma(const __half* __restrict__ Ah, const __half* __restrict__ Al,
         const __half* __restrict__ Bh, const __half* __restrict__ Bl,
         const float* __restrict__ bias, float* __restrict__ C,
         int K, int ldc, int Nstore)
{
    extern __shared__ char smem[];
    uint32_t sbase = smem_u32(smem);
    int tid = threadIdx.x, wid = tid >> 5, lid = tid & 31;
    int wm = wid & 3, wn = wid >> 2;       // 4 warps along M, 2 along N
    int row0 = blockIdx.y * 128;
    int col0 = blockIdx.x * 128;

    float acc[2][8][4];
#pragma unroll
    for (int i = 0; i < 2; i++)
#pragma unroll
        for (int j = 0; j < 8; j++)
#pragma unroll
            for (int q = 0; q < 4; q++) acc[i][j][q] = 0.0f;

    const int KITER = K >> 6;
    load_stage(sbase, Ah, Al, Bh, Bl, row0, col0, 0, K, tid);
    load_stage(sbase + STG, Ah, Al, Bh, Bl, row0, col0, 64, K, tid);

    // per-lane ldmatrix row/col components
    int lrow = lid & 15;                   // row within 16-row frag
    int kadd = (lid & 16) ? 8 : 0;         // col-half +8 for upper lanes

    for (int i = 0; i < KITER; i++) {
        asm volatile("cp.async.wait_group 1;" ::: "memory");
        __syncthreads();
        uint32_t stg = sbase + (i & 1) * STG;
        uint32_t Abh = stg, Abl = stg + 16384, Bbh = stg + 32768, Bbl = stg + 49152;

#pragma unroll
        for (int ks = 0; ks < 4; ks++) {
            int col = ks * 16 + kadd;      // half index within BK=64
            uint32_t ahi[2][4], alo[2][4];
#pragma unroll
            for (int mi = 0; mi < 2; mi++) {
                int r = wm * 32 + mi * 16 + lrow;
                uint32_t off = SWZ(r * 128 + col * 2);
                ldsm4(ahi[mi], Abh + off);
                ldsm4(alo[mi], Abl + off);
            }
            uint32_t bhi[4][4], blo[4][4];
#pragma unroll
            for (int j = 0; j < 4; j++) {
                int r = wn * 64 + j * 16 + lrow;
                uint32_t off = SWZ(r * 128 + col * 2);
                ldsm4(bhi[j], Bbh + off);
                ldsm4(blo[j], Bbl + off);
            }
            // regs: {r0,r1,r2,r3} = (n0..7,k0..7),(n8..15,k0..7),(n0..7,k8..15),(n8..15,k8..15)
            // b-frag for n8 group 2j   = {r0, r2}; group 2j+1 = {r1, r3}
#pragma unroll
            for (int mi = 0; mi < 2; mi++)
#pragma unroll
                for (int j = 0; j < 4; j++) {
                    mma16816(acc[mi][2 * j],     ahi[mi], bhi[j][0], bhi[j][2]);
                    mma16816(acc[mi][2 * j + 1], ahi[mi], bhi[j][1], bhi[j][3]);
                    mma16816(acc[mi][2 * j],     ahi[mi], blo[j][0], blo[j][2]);
                    mma16816(acc[mi][2 * j + 1], ahi[mi], blo[j][1], blo[j][3]);
                    mma16816(acc[mi][2 * j],     alo[mi], bhi[j][0], bhi[j][2]);
                    mma16816(acc[mi][2 * j + 1], alo[mi], bhi[j][1], bhi[j][3]);
                }
        }
        __syncthreads();
        if (i + 2 < KITER)
            load_stage(stg, Ah, Al, Bh, Bl, row0, col0, (i + 2) * 64, K, tid);
        else
            asm volatile("cp.async.commit_group;" ::: "memory");
    }

    // epilogue: C layout m16n8 — thread lid: rows lid/4 and lid/4+8, cols 2*(lid&3)
    int trow = lid >> 2, tcol = (lid & 3) * 2;
#pragma unroll
    for (int mi = 0; mi < 2; mi++) {
#pragma unroll
        for (int j = 0; j < 8; j++) {
            int gc = col0 + wn * 64 + j * 8 + tcol;
            if (gc >= Nstore) continue;
            int gr0 = row0 + wm * 32 + mi * 16 + trow;
            float2 v0 = make_float2(acc[mi][j][0], acc[mi][j][1]);
            float2 v1 = make_float2(acc[mi][j][2], acc[mi][j][3]);
            if (gr0 % 5 == 0)       { v0.x += bias[gc]; v0.y += bias[gc + 1]; }
            if ((gr0 + 8) % 5 == 0) { v1.x += bias[gc]; v1.y += bias[gc + 1]; }
            *(float2*)(C + (size_t)gr0 * ldc + gc) = v0;
            *(float2*)(C + (size_t)(gr0 + 8) * ldc + gc) = v1;
        }
    }
}

// ---------------- head: softmax-mixture derivative, warp per point ---------
__global__ void finalize_kernel(const float* __restrict__ OUT,
                                float* __restrict__ y, int B)
{
    int warp = (blockIdx.x * blockDim.x + threadIdx.x) >> 5;
    int lane = threadIdx.x & 31;
    if (warp >= B) return;
    const float* o = OUT + (size_t)warp * 5 * ODIM;

    float l0 = o[lane], l1 = o[lane + 32];
    float m = fmaxf(l0, l1);
#pragma unroll
    for (int s = 16; s; s >>= 1) m = fmaxf(m, __shfl_xor_sync(0xFFFFFFFFu, m, s));
    float e0 = expf(l0 - m), e1 = expf(l1 - m);
    float S = e0 + e1;
#pragma unroll
    for (int s = 16; s; s >>= 1) S += __shfl_xor_sync(0xFFFFFFFFu, S, s);
    float s0 = e0 / S, s1 = e1 / S;

    float v0[6], v1[6];
#pragma unroll
    for (int t = 0; t < 6; t++) {
        v0[t] = o[64 + 6 * lane + t];
        v1[t] = o[64 + 6 * (lane + 32) + t];
    }

    float Dm[4][6];
#pragma unroll
    for (int j = 0; j < 4; j++) {
        const float* tj = o + (size_t)(j + 1) * ODIM;
        float g0 = tj[lane], g1 = tj[lane + 32];
        float dot = s0 * g0 + s1 * g1;
#pragma unroll
        for (int s = 16; s; s >>= 1) dot += __shfl_xor_sync(0xFFFFFFFFu, dot, s);
#pragma unroll
        for (int t = 0; t < 6; t++) {
            float dv0 = tj[64 + 6 * lane + t];
            float dv1 = tj[64 + 6 * (lane + 32) + t];
            float val = s0 * fmaf(g0 - dot, v0[t], dv0) + s1 * fmaf(g1 - dot, v1[t], dv1);
#pragma unroll
            for (int s = 16; s; s >>= 1) val += __shfl_xor_sync(0xFFFFFFFFu, val, s);
            Dm[j][t] = val;
        }
    }
    if (lane == 0) {
        float u0 =  Dm[1][0] + Dm[2][1] + Dm[3][2];
        float u1 = -Dm[0][0] + Dm[2][3] + Dm[3][4];
        float u2 = -Dm[0][1] - Dm[1][3] + Dm[3][5];
        float u3 = -Dm[0][2] - Dm[1][4] - Dm[2][5];
        *(float4*)(y + (size_t)warp * 4) = make_float4(u0 * 10.0f, u1, u2, u3);
    }
}

// ---------------------------------------------------------------------------
extern "C" void kernel_launch(void* const* d_in, const int* in_sizes, int n_in,
                              void* d_out, int out_size)
{
    const float* x    = (const float*)d_in[0];
    const float* W0   = (const float*)d_in[1];
    const float* b0   = (const float*)d_in[2];
    const float* Wh   = (const float*)d_in[3];
    const float* bh   = (const float*)d_in[4];
    const float* Wout = (const float*)d_in[5];
    const float* bout = (const float*)d_in[6];
    float* y = (float*)d_out;

    int B = in_sizes[0] / 4;
    int M = B * 5;

    __half *Ah, *Al, *WThi, *WTlo;
    float *PRE, *OUTB;
    cudaGetSymbolAddress((void**)&Ah, g_Ah);
    cudaGetSymbolAddress((void**)&Al, g_Al);
    cudaGetSymbolAddress((void**)&PRE, g_PRE);
    cudaGetSymbolAddress((void**)&OUTB, g_OUT);
    cudaGetSymbolAddress((void**)&WThi, g_WThi);
    cudaGetSymbolAddress((void**)&WTlo, g_WTlo);

    static int smem_set = 0;
    if (!smem_set) {
        cudaFuncSetAttribute(gemm_mma, cudaFuncAttributeMaxDynamicSharedMemorySize, 2 * STG);
        smem_set = 1;
    }

    // weight prep: transpose + split
    prep_transpose<<<dim3(32, 32, NLAY), dim3(32, 8)>>>(Wh, WThi, WTlo, DM, DM);
    prep_transpose<<<dim3(ODIM / 32, 32, 1), dim3(32, 8)>>>(
        Wout, WThi + (size_t)NLAY * DM * DM, WTlo + (size_t)NLAY * DM * DM, DM, ODIM);

    // layer 0
    layer0_kernel<<<(B * 256 + 255) / 256, 256>>>(x, W0, b0, Ah, Al, B);

    // hidden layers
    dim3 gH(DM / 128, M / 128);
    for (int l = 0; l < NLAY; l++) {
        gemm_mma<<<gH, 256, 2 * STG>>>(Ah, Al,
            WThi + (size_t)l * DM * DM, WTlo + (size_t)l * DM * DM,
            bh + (size_t)l * DM, PRE, DM, DM, DM);
        act_kernel<<<(B * 256 + 255) / 256, 256>>>(PRE, Ah, Al, B);
    }

    // output layer: WT padded to 512 rows (rows 448..511 zero)
    dim3 gO(4, M / 128);
    gemm_mma<<<gO, 256, 2 * STG>>>(Ah, Al,
        WThi + (size_t)NLAY * DM * DM, WTlo + (size_t)NLAY * DM * DM,
        bout, OUTB, DM, ODIM, ODIM);

    // head
    finalize_kernel<<<(B * 32 + 255) / 256, 256>>>(OUTB, y, B);
}